// round 4
// baseline (speedup 1.0000x reference)
#include <cuda_runtime.h>

#define NN 64
#define CC 128
#define TT 2048
#define SS 9
#define CT 8              // output channels per block tile
#define JW (CT + SS - 1)  // 16 contributing input channel rows
#define THREADS 128

__device__ float g_sum[CC];
__device__ float g_sqs[CC];
__device__ float g_scale[CC];
__device__ float g_bias[CC];

__global__ void zero_stats_kernel() {
    int i = threadIdx.x;
    if (i < CC) { g_sum[i] = 0.0f; g_sqs[i] = 0.0f; }
}

__global__ __launch_bounds__(THREADS)
void conv_stats_kernel(const float* __restrict__ x,
                       const float* __restrict__ w,
                       float* __restrict__ out) {
    // grid: (CC/CT, NN). Each block: CT output channels, full T row of batch n.
    const int c0 = blockIdx.x * CT;
    const int n  = blockIdx.y;
    const int tid = threadIdx.x;

    // weights for this channel tile -> registers (uniform across block)
    float wr[CT][SS];
    #pragma unroll
    for (int dc = 0; dc < CT; dc++)
        #pragma unroll
        for (int s = 0; s < SS; s++)
            wr[dc][s] = __ldg(&w[(c0 + dc) * SS + s]);

    // contributing row j -> channel cc = c0 - 4 + j.
    // x value used at output time t is x[cc, t - sh(cc)], sh(cc) = cc%9 - 4,
    // zero if (t - sh) outside [0, TT) or cc outside [0, CC).
    int baseIdx[JW];   // cc * TT
    int shv[JW];       // shift; poisoned so predicate always fails for invalid cc
    #pragma unroll
    for (int j = 0; j < JW; j++) {
        int cc = c0 - (SS / 2) + j;
        if (cc >= 0 && cc < CC) {
            baseIdx[j] = cc * TT;
            shv[j]     = (cc % SS) - (SS / 2);   // in [-4, 4]
        } else {
            baseIdx[j] = 0;
            shv[j]     = 1 << 28;                // (unsigned)(t - shv) >= TT always
        }
    }

    const float* xbase = x + (size_t)n * CC * TT;
    float* obase = out + ((size_t)n * CC + c0) * TT;

    float ssum[CT], ssq[CT];
    #pragma unroll
    for (int dc = 0; dc < CT; dc++) { ssum[dc] = 0.0f; ssq[dc] = 0.0f; }

    for (int t = tid; t < TT; t += THREADS) {
        // gather the 16 contributing x values (independent loads -> high MLP)
        float xv[JW];
        #pragma unroll
        for (int j = 0; j < JW; j++) {
            int ti = t - shv[j];
            xv[j] = ((unsigned)ti < (unsigned)TT) ? __ldg(xbase + baseIdx[j] + ti)
                                                  : 0.0f;
        }
        float acc[CT];
        #pragma unroll
        for (int dc = 0; dc < CT; dc++) acc[dc] = 0.0f;
        #pragma unroll
        for (int j = 0; j < JW; j++) {
            #pragma unroll
            for (int dc = 0; dc < CT; dc++) {
                int s = j - dc;               // tap index for output channel dc
                if (s >= 0 && s < SS)
                    acc[dc] = fmaf(wr[dc][s], xv[j], acc[dc]);
            }
        }
        #pragma unroll
        for (int dc = 0; dc < CT; dc++) {
            obase[(size_t)dc * TT + t] = acc[dc];
            ssum[dc] += acc[dc];
            ssq[dc]   = fmaf(acc[dc], acc[dc], ssq[dc]);
        }
    }

    // ---- per-channel reduction: warp shuffle -> smem -> global atomics ----
    __shared__ float sred[THREADS / 32][2 * CT];
    const int lane = tid & 31;
    const int wz   = tid >> 5;
    #pragma unroll
    for (int dc = 0; dc < CT; dc++) {
        float a = ssum[dc], b = ssq[dc];
        #pragma unroll
        for (int off = 16; off > 0; off >>= 1) {
            a += __shfl_xor_sync(0xFFFFFFFFu, a, off);
            b += __shfl_xor_sync(0xFFFFFFFFu, b, off);
        }
        if (lane == 0) { sred[wz][dc] = a; sred[wz][CT + dc] = b; }
    }
    __syncthreads();
    if (tid < 2 * CT) {
        float a = 0.0f;
        #pragma unroll
        for (int k = 0; k < THREADS / 32; k++) a += sred[k][tid];
        if (tid < CT) atomicAdd(&g_sum[c0 + tid], a);
        else          atomicAdd(&g_sqs[c0 + tid - CT], a);
    }
}

__global__ void finalize_kernel(const float* __restrict__ gamma,
                                const float* __restrict__ beta) {
    int c = threadIdx.x;
    if (c < CC) {
        const float invM = 1.0f / (float)((size_t)NN * TT);
        float m  = g_sum[c] * invM;
        float v  = g_sqs[c] * invM - m * m;
        float is = rsqrtf(v + 1e-5f);
        float sc = gamma[c] * is;
        g_scale[c] = sc;
        g_bias[c]  = beta[c] - m * sc;
    }
}

__global__ __launch_bounds__(256)
void normalize_kernel(float* __restrict__ out) {
    size_t i = ((size_t)blockIdx.x * blockDim.x + threadIdx.x) * 4;
    int c = (int)((i >> 11) & (CC - 1));   // T = 2048 = 2^11
    float sc = g_scale[c], bi = g_bias[c];
    float4 v = *reinterpret_cast<float4*>(out + i);
    v.x = fmaxf(fmaf(v.x, sc, bi), 0.0f);
    v.y = fmaxf(fmaf(v.y, sc, bi), 0.0f);
    v.z = fmaxf(fmaf(v.z, sc, bi), 0.0f);
    v.w = fmaxf(fmaf(v.w, sc, bi), 0.0f);
    *reinterpret_cast<float4*>(out + i) = v;
}

extern "C" void kernel_launch(void* const* d_in, const int* in_sizes, int n_in,
                              void* d_out, int out_size) {
    const float* x     = (const float*)d_in[0];   // (64,128,2048) f32
    const float* cw    = (const float*)d_in[1];   // (128,9)       f32
    const float* gamma = (const float*)d_in[2];   // (128,)        f32
    const float* beta  = (const float*)d_in[3];   // (128,)        f32
    float* out = (float*)d_out;                   // (64,128,2048) f32

    zero_stats_kernel<<<1, 128>>>();
    dim3 grid(CC / CT, NN);
    conv_stats_kernel<<<grid, THREADS>>>(x, cw, out);
    finalize_kernel<<<1, 128>>>(gamma, beta);
    size_t total = (size_t)NN * CC * TT;          // 16777216
    normalize_kernel<<<(unsigned)(total / 4 / 256), 256>>>(out);
}